// round 2
// baseline (speedup 1.0000x reference)
#include <cuda_runtime.h>

// LightCSCF: bpr + reg + cscf losses.
// total = e1@e2^T + e1@e1^T = e1 @ (e1+e2)^T -> single 8192x8192x64 GEMM,
// fused epilogue g(x) = exp(x/T) + max(1, exp(x/T)*exp(-m/T)), fused row-sum.
// R2: inner product via packed fma.rn.f32x2 (Blackwell FFMA2, 2 MACs/instr).
//     A tile stored DUPLICATED in smem so one LDS.64 yields a replicated
//     (a,a) pack; B pairs come free from contiguous LDS.128.

#define BATCH 8192
#define DIM   64
#define NCB   64        // 8192 / 128 column blocks
#define KS    16        // k-slice per smem stage
#define PADA  258       // a_dup pitch in floats (129 float2) - 2-way store conflict max
#define PADB  132       // b pitch in floats, 16B-aligned reads

typedef unsigned long long ull;

__device__ float g_e1[BATCH * DIM];       // normalized user embeddings
__device__ float g_f [BATCH * DIM];       // e1 + e2
__device__ float g_pos[BATCH];            // cscf pos_score per row
__device__ float g_bpr[BATCH];            // log_sigmoid(pos-neg) per row
__device__ float g_sq [BATCH];            // sum-of-squares per row
__device__ float g_partial[BATCH * NCB];  // row-sum partials per column block
__device__ float g_blk[NCB * 3];          // per-block (loss, bpr, sq) sums

// ---------------------------------------------------------------------------
// Kernel 1: gather + per-row stats + normalized vectors. One warp per row.
// ---------------------------------------------------------------------------
__global__ void __launch_bounds__(256) prep_kernel(
    const float* __restrict__ ut, const float* __restrict__ it,
    const int* __restrict__ user, const int* __restrict__ pos,
    const int* __restrict__ neg)
{
    int row  = blockIdx.x * 8 + (threadIdx.x >> 5);
    int lane = threadIdx.x & 31;

    const float2* up  = (const float2*)(ut + (long long)user[row] * DIM);
    const float2* pp  = (const float2*)(it + (long long)pos[row]  * DIM);
    const float2* npp = (const float2*)(it + (long long)neg[row]  * DIM);
    float2 u = up[lane], p = pp[lane], n = npp[lane];

    float s_up = u.x * p.x + u.y * p.y;
    float s_un = u.x * n.x + u.y * n.y;
    float s_uu = u.x * u.x + u.y * u.y;
    float s_pp = p.x * p.x + p.y * p.y;
    float s_nn = n.x * n.x + n.y * n.y;

    #pragma unroll
    for (int off = 16; off; off >>= 1) {
        s_up += __shfl_xor_sync(0xffffffffu, s_up, off);
        s_un += __shfl_xor_sync(0xffffffffu, s_un, off);
        s_uu += __shfl_xor_sync(0xffffffffu, s_uu, off);
        s_pp += __shfl_xor_sync(0xffffffffu, s_pp, off);
        s_nn += __shfl_xor_sync(0xffffffffu, s_nn, off);
    }

    float inu = 1.0f / fmaxf(sqrtf(s_uu), 1e-12f);
    float inp = 1.0f / fmaxf(sqrtf(s_pp), 1e-12f);

    float2 e1; e1.x = u.x * inu; e1.y = u.y * inu;
    float2 e2; e2.x = p.x * inp; e2.y = p.y * inp;
    ((float2*)(g_e1 + row * DIM))[lane] = e1;
    float2 f; f.x = e1.x + e2.x; f.y = e1.y + e2.y;
    ((float2*)(g_f + row * DIM))[lane] = f;

    if (lane == 0) {
        float sim = s_up * inu * inp;
        float t = __expf(sim * 5.0f);
        g_pos[row] = t + fmaxf(1.0f, t * 0.0183156393f);
        float x = s_up - s_un;
        g_bpr[row] = fminf(x, 0.0f) - log1pf(__expf(-fabsf(x)));
        g_sq[row] = s_uu + s_pp + s_nn;
    }
}

// ---------------------------------------------------------------------------
// Kernel 2: fused GEMM total = e1 @ f^T, epilogue + row-sum.
// 128x128 tile per CTA, 256 threads, 4x16 per thread (packed pairs on cols).
// ---------------------------------------------------------------------------
__global__ void __launch_bounds__(256) gemm_kernel()
{
    __shared__ __align__(16) float a_dup[KS * PADA];  // duplicated: (a,a) pairs
    __shared__ __align__(16) float b_s  [KS * PADB];

    int tid = threadIdx.x;
    int tx = tid & 7;       // col-group 0..7  -> cols tx*16 .. +15
    int ty = tid >> 3;      // row-group 0..31 -> rows ty*4 .. +3
    int rowBase = blockIdx.y * 128;
    int colBase = blockIdx.x * 128;

    ull acc[4][8];          // packed f32x2 accumulators: [row][col-pair]
    #pragma unroll
    for (int i = 0; i < 4; i++)
        #pragma unroll
        for (int j = 0; j < 8; j++) acc[i][j] = 0ull;

    #pragma unroll
    for (int kb = 0; kb < DIM; kb += KS) {
        __syncthreads();
        // Load stage: coalesced global reads, k-major smem tiles.
        #pragma unroll
        for (int l = 0; l < 8; l++) {
            int i = tid + l * 256;       // 0..2047
            int r = i >> 4;              // 0..127
            int k = i & 15;              // 0..15
            float va = g_e1[(rowBase + r) * DIM + kb + k];
            ((float2*)(a_dup + k * PADA))[r] = make_float2(va, va);
            b_s[k * PADB + r] = g_f[(colBase + r) * DIM + kb + k];
        }
        __syncthreads();

        #pragma unroll
        for (int k = 0; k < KS; k++) {
            ull ap[4];
            #pragma unroll
            for (int i = 0; i < 4; i++)
                ap[i] = *(const ull*)&a_dup[k * PADA + 2 * (ty * 4 + i)];
            ull bp[8];
            #pragma unroll
            for (int c = 0; c < 4; c++) {
                ulonglong2 v = *(const ulonglong2*)&b_s[k * PADB + tx * 16 + c * 4];
                bp[c * 2]     = v.x;
                bp[c * 2 + 1] = v.y;
            }
            #pragma unroll
            for (int i = 0; i < 4; i++)
                #pragma unroll
                for (int j = 0; j < 8; j++)
                    asm("fma.rn.f32x2 %0, %1, %2, %0;"
                        : "+l"(acc[i][j]) : "l"(ap[i]), "l"(bp[j]));
        }
    }

    // Epilogue: g(x) = t + max(1, t*C), t = exp(5x); reduce the 16 cols,
    // then across the 8 threads (tx) sharing each row.
    #pragma unroll
    for (int i = 0; i < 4; i++) {
        float rs = 0.0f;
        #pragma unroll
        for (int j = 0; j < 8; j++) {
            float lo = __uint_as_float((unsigned)(acc[i][j] & 0xffffffffu));
            float hi = __uint_as_float((unsigned)(acc[i][j] >> 32));
            float t0 = __expf(lo * 5.0f);
            rs += t0 + fmaxf(1.0f, t0 * 0.0183156393f);
            float t1 = __expf(hi * 5.0f);
            rs += t1 + fmaxf(1.0f, t1 * 0.0183156393f);
        }
        #pragma unroll
        for (int off = 4; off; off >>= 1)
            rs += __shfl_down_sync(0xffffffffu, rs, off, 8);
        if (tx == 0)
            g_partial[(rowBase + ty * 4 + i) * NCB + blockIdx.x] = rs;
    }
}

// ---------------------------------------------------------------------------
// Kernel 3: per-row loss + per-block partial sums (deterministic).
// ---------------------------------------------------------------------------
__global__ void __launch_bounds__(128) rowloss_kernel()
{
    int tid = threadIdx.x;
    int row = blockIdx.x * 128 + tid;

    const float4* pp = (const float4*)(g_partial + row * NCB);
    float rs = 0.0f;
    #pragma unroll
    for (int i = 0; i < NCB / 4; i++) {
        float4 v = pp[i];
        rs += v.x + v.y + v.z + v.w;
    }
    float loss = -logf(g_pos[row] / rs + 1e-5f);
    float bpr = g_bpr[row];
    float sq  = g_sq[row];

    __shared__ float sl[128], sb[128], ss[128];
    sl[tid] = loss; sb[tid] = bpr; ss[tid] = sq;
    __syncthreads();
    #pragma unroll
    for (int s = 64; s; s >>= 1) {
        if (tid < s) {
            sl[tid] += sl[tid + s];
            sb[tid] += sb[tid + s];
            ss[tid] += ss[tid + s];
        }
        __syncthreads();
    }
    if (tid == 0) {
        g_blk[blockIdx.x * 3 + 0] = sl[0];
        g_blk[blockIdx.x * 3 + 1] = sb[0];
        g_blk[blockIdx.x * 3 + 2] = ss[0];
    }
}

// ---------------------------------------------------------------------------
// Kernel 4: final reduction -> (bpr, reg, na)
// ---------------------------------------------------------------------------
__global__ void final_kernel(float* __restrict__ out)
{
    int t = threadIdx.x;  // 32 threads
    float l = 0.0f, b = 0.0f, s = 0.0f;
    for (int i = t; i < NCB; i += 32) {
        l += g_blk[i * 3 + 0];
        b += g_blk[i * 3 + 1];
        s += g_blk[i * 3 + 2];
    }
    #pragma unroll
    for (int off = 16; off; off >>= 1) {
        l += __shfl_xor_sync(0xffffffffu, l, off);
        b += __shfl_xor_sync(0xffffffffu, b, off);
        s += __shfl_xor_sync(0xffffffffu, s, off);
    }
    if (t == 0) {
        out[0] = -b / (float)BATCH;                  // bpr
        out[1] = 1e-4f * 0.5f * s / (float)BATCH;    // reg
        out[2] = 0.5f * l / (float)BATCH;            // na
    }
}

extern "C" void kernel_launch(void* const* d_in, const int* in_sizes, int n_in,
                              void* d_out, int out_size)
{
    const float* ut  = (const float*)d_in[0];
    const float* it  = (const float*)d_in[1];
    const int* user  = (const int*)d_in[2];
    const int* pos   = (const int*)d_in[3];
    const int* neg   = (const int*)d_in[4];

    prep_kernel<<<BATCH / 8, 256>>>(ut, it, user, pos, neg);
    dim3 grid(NCB, NCB);
    gemm_kernel<<<grid, 256>>>();
    rowloss_kernel<<<NCB, 128>>>();
    final_kernel<<<1, 32>>>((float*)d_out);
}

// round 3
// speedup vs baseline: 8.7343x; 8.7343x over previous
#include <cuda_runtime.h>
#include <cuda_bf16.h>

// LightCSCF: bpr + reg + cscf losses.
// total = e1@e2^T + e1@e1^T = e1 @ (e1+e2)^T -> single 8192x8192x64 GEMM,
// fused epilogue g(x) = exp(x/T) + max(1, exp(x/T)*exp(-m/T)), fused row-sum.
// R3: GEMM on the tensor pipe via bf16 mma.sync.m16n8k16 (fp32 accumulate).
//     bpr/reg/pos-score stay full fp32. Only the 67M-element score matrix
//     (which is summed, so rounding averages out) uses bf16 inputs.

#define BATCH 8192
#define DIM   64
#define NCB   64          // 8192 / 128 column blocks
#define PITCH 72          // smem row pitch in bf16 (144B = 9 x 16B -> ldmatrix conflict-free)

__device__ __nv_bfloat16 g_e1h[BATCH * DIM]; // normalized user embeddings (bf16)
__device__ __nv_bfloat16 g_fh [BATCH * DIM]; // e1 + e2 (bf16)
__device__ float g_pos[BATCH];               // cscf pos_score per row (fp32)
__device__ float g_bpr[BATCH];               // log_sigmoid(pos-neg) per row
__device__ float g_sq [BATCH];               // sum-of-squares per row
__device__ float g_partial[BATCH * NCB];     // row-sum partials per column block
__device__ float g_blk[NCB * 3];             // per-block (loss, bpr, sq) sums

__device__ __forceinline__ unsigned smem_u32(const void* p) {
    return (unsigned)__cvta_generic_to_shared(p);
}

// ---------------------------------------------------------------------------
// Kernel 1: gather + per-row stats + normalized bf16 vectors. One warp per row.
// ---------------------------------------------------------------------------
__global__ void __launch_bounds__(256) prep_kernel(
    const float* __restrict__ ut, const float* __restrict__ it,
    const int* __restrict__ user, const int* __restrict__ pos,
    const int* __restrict__ neg)
{
    int row  = blockIdx.x * 8 + (threadIdx.x >> 5);
    int lane = threadIdx.x & 31;

    const float2* up  = (const float2*)(ut + (long long)user[row] * DIM);
    const float2* pp  = (const float2*)(it + (long long)pos[row]  * DIM);
    const float2* npp = (const float2*)(it + (long long)neg[row]  * DIM);
    float2 u = up[lane], p = pp[lane], n = npp[lane];

    float s_up = u.x * p.x + u.y * p.y;
    float s_un = u.x * n.x + u.y * n.y;
    float s_uu = u.x * u.x + u.y * u.y;
    float s_pp = p.x * p.x + p.y * p.y;
    float s_nn = n.x * n.x + n.y * n.y;

    #pragma unroll
    for (int off = 16; off; off >>= 1) {
        s_up += __shfl_xor_sync(0xffffffffu, s_up, off);
        s_un += __shfl_xor_sync(0xffffffffu, s_un, off);
        s_uu += __shfl_xor_sync(0xffffffffu, s_uu, off);
        s_pp += __shfl_xor_sync(0xffffffffu, s_pp, off);
        s_nn += __shfl_xor_sync(0xffffffffu, s_nn, off);
    }

    float inu = 1.0f / fmaxf(sqrtf(s_uu), 1e-12f);
    float inp = 1.0f / fmaxf(sqrtf(s_pp), 1e-12f);

    float2 e1; e1.x = u.x * inu; e1.y = u.y * inu;
    float2 e2; e2.x = p.x * inp; e2.y = p.y * inp;
    float2 f;  f.x  = e1.x + e2.x; f.y = e1.y + e2.y;

    ((__nv_bfloat162*)(g_e1h + row * DIM))[lane] =
        __floats2bfloat162_rn(e1.x, e1.y);
    ((__nv_bfloat162*)(g_fh  + row * DIM))[lane] =
        __floats2bfloat162_rn(f.x, f.y);

    if (lane == 0) {
        float sim = s_up * inu * inp;
        float t = __expf(sim * 5.0f);
        g_pos[row] = t + fmaxf(1.0f, t * 0.0183156393f);
        float x = s_up - s_un;
        g_bpr[row] = fminf(x, 0.0f) - log1pf(__expf(-fabsf(x)));
        g_sq[row] = s_uu + s_pp + s_nn;
    }
}

// ---------------------------------------------------------------------------
// Kernel 2: tensor-core GEMM total = e1 @ f^T, fused epilogue + row-sum.
// 128x128 tile per CTA, 8 warps (4x2 grid), warp tile 32x64.
// Both operands row-major [*, K=64]  ->  mma m16n8k16.row.col.
// ---------------------------------------------------------------------------
__global__ void __launch_bounds__(256) gemm_kernel()
{
    __shared__ __align__(16) __nv_bfloat16 a_s[128 * PITCH];
    __shared__ __align__(16) __nv_bfloat16 b_s[128 * PITCH];
    __shared__ float rowsum[2][128];

    int tid = threadIdx.x;
    int rowBase = blockIdx.y * 128;
    int colBase = blockIdx.x * 128;

    // Stage full 128x64 bf16 tiles (16KB each) into smem. uint4 = 8 bf16.
    const uint4* ga = (const uint4*)g_e1h;
    const uint4* gb = (const uint4*)g_fh;
    #pragma unroll
    for (int l = 0; l < 4; l++) {
        int i = tid + l * 256;       // 0..1023
        int r = i >> 3;              // 0..127
        int c = i & 7;               // 0..7 (16B chunks)
        *(uint4*)&a_s[r * PITCH + c * 8] = ga[(rowBase + r) * 8 + c];
        *(uint4*)&b_s[r * PITCH + c * 8] = gb[(colBase + r) * 8 + c];
    }
    __syncthreads();

    int wid  = tid >> 5;
    int lane = tid & 31;
    int wy = wid >> 1;   // 0..3 -> rows wy*32 .. +31
    int wx = wid & 1;    // 0..1 -> cols wx*64 .. +63

    float acc[2][8][4];
    #pragma unroll
    for (int mf = 0; mf < 2; mf++)
        #pragma unroll
        for (int nf = 0; nf < 8; nf++)
            #pragma unroll
            for (int q = 0; q < 4; q++) acc[mf][nf][q] = 0.0f;

    // ldmatrix base addresses: lane&15 selects the matrix row, lane>>4 the
    // 16B k-chunk (k-halves of a k16 step).
    unsigned a_base = smem_u32(a_s) +
        (wy * 32 + (lane & 15)) * (PITCH * 2) + (lane >> 4) * 16;
    unsigned b_base = smem_u32(b_s) +
        (wx * 64 + (lane & 15)) * (PITCH * 2) + (lane >> 4) * 16;

    #pragma unroll
    for (int s = 0; s < 4; s++) {            // k16 steps over K=64
        unsigned koff = s * 32;              // 16 bf16 = 32B per step

        unsigned af[2][4];
        #pragma unroll
        for (int mf = 0; mf < 2; mf++) {
            unsigned addr = a_base + mf * 16 * (PITCH * 2) + koff;
            asm volatile("ldmatrix.sync.aligned.m8n8.x4.shared.b16 "
                         "{%0,%1,%2,%3}, [%4];"
                         : "=r"(af[mf][0]), "=r"(af[mf][1]),
                           "=r"(af[mf][2]), "=r"(af[mf][3])
                         : "r"(addr));
        }

        unsigned bf[8][2];
        #pragma unroll
        for (int g = 0; g < 4; g++) {        // 16 n per ldmatrix.x4
            unsigned addr = b_base + g * 16 * (PITCH * 2) + koff;
            unsigned r0, r1, r2, r3;
            asm volatile("ldmatrix.sync.aligned.m8n8.x4.shared.b16 "
                         "{%0,%1,%2,%3}, [%4];"
                         : "=r"(r0), "=r"(r1), "=r"(r2), "=r"(r3)
                         : "r"(addr));
            bf[g * 2 + 0][0] = r0; bf[g * 2 + 0][1] = r2;
            bf[g * 2 + 1][0] = r1; bf[g * 2 + 1][1] = r3;
        }

        #pragma unroll
        for (int mf = 0; mf < 2; mf++)
            #pragma unroll
            for (int nf = 0; nf < 8; nf++)
                asm volatile(
                    "mma.sync.aligned.m16n8k16.row.col.f32.bf16.bf16.f32 "
                    "{%0,%1,%2,%3}, {%4,%5,%6,%7}, {%8,%9}, {%0,%1,%2,%3};"
                    : "+f"(acc[mf][nf][0]), "+f"(acc[mf][nf][1]),
                      "+f"(acc[mf][nf][2]), "+f"(acc[mf][nf][3])
                    : "r"(af[mf][0]), "r"(af[mf][1]),
                      "r"(af[mf][2]), "r"(af[mf][3]),
                      "r"(bf[nf][0]), "r"(bf[nf][1]));
    }

    // Epilogue: g(x) = t + max(1, t*C), t = exp(5x); fused row-sum.
    // Acc layout: regs {0,1} -> row lane>>2, cols 2c,2c+1; regs {2,3} -> row +8.
    #pragma unroll
    for (int mf = 0; mf < 2; mf++) {
        float rs0 = 0.0f, rs1 = 0.0f;
        #pragma unroll
        for (int nf = 0; nf < 8; nf++) {
            #pragma unroll
            for (int q = 0; q < 2; q++) {
                float t = __expf(acc[mf][nf][q] * 5.0f);
                rs0 += t + fmaxf(1.0f, t * 0.0183156393f);
            }
            #pragma unroll
            for (int q = 2; q < 4; q++) {
                float t = __expf(acc[mf][nf][q] * 5.0f);
                rs1 += t + fmaxf(1.0f, t * 0.0183156393f);
            }
        }
        // Reduce across the 4 lanes (lane&3) sharing each row.
        #pragma unroll
        for (int off = 1; off <= 2; off <<= 1) {
            rs0 += __shfl_xor_sync(0xffffffffu, rs0, off);
            rs1 += __shfl_xor_sync(0xffffffffu, rs1, off);
        }
        if ((lane & 3) == 0) {
            int r = wy * 32 + mf * 16 + (lane >> 2);
            rowsum[wx][r]     = rs0;
            rowsum[wx][r + 8] = rs1;
        }
    }
    __syncthreads();

    if (tid < 128)
        g_partial[(rowBase + tid) * NCB + blockIdx.x] =
            rowsum[0][tid] + rowsum[1][tid];
}

// ---------------------------------------------------------------------------
// Kernel 3: per-row loss + per-block partial sums (deterministic).
// ---------------------------------------------------------------------------
__global__ void __launch_bounds__(128) rowloss_kernel()
{
    int tid = threadIdx.x;
    int row = blockIdx.x * 128 + tid;

    const float4* pp = (const float4*)(g_partial + row * NCB);
    float rs = 0.0f;
    #pragma unroll
    for (int i = 0; i < NCB / 4; i++) {
        float4 v = pp[i];
        rs += v.x + v.y + v.z + v.w;
    }
    float loss = -logf(g_pos[row] / rs + 1e-5f);
    float bpr = g_bpr[row];
    float sq  = g_sq[row];

    __shared__ float sl[128], sb[128], ss[128];
    sl[tid] = loss; sb[tid] = bpr; ss[tid] = sq;
    __syncthreads();
    #pragma unroll
    for (int s = 64; s; s >>= 1) {
        if (tid < s) {
            sl[tid] += sl[tid + s];
            sb[tid] += sb[tid + s];
            ss[tid] += ss[tid + s];
        }
        __syncthreads();
    }
    if (tid == 0) {
        g_blk[blockIdx.x * 3 + 0] = sl[0];
        g_blk[blockIdx.x * 3 + 1] = sb[0];
        g_blk[blockIdx.x * 3 + 2] = ss[0];
    }
}

// ---------------------------------------------------------------------------
// Kernel 4: final reduction -> (bpr, reg, na)
// ---------------------------------------------------------------------------
__global__ void final_kernel(float* __restrict__ out)
{
    int t = threadIdx.x;  // 32 threads
    float l = 0.0f, b = 0.0f, s = 0.0f;
    for (int i = t; i < NCB; i += 32) {
        l += g_blk[i * 3 + 0];
        b += g_blk[i * 3 + 1];
        s += g_blk[i * 3 + 2];
    }
    #pragma unroll
    for (int off = 16; off; off >>= 1) {
        l += __shfl_xor_sync(0xffffffffu, l, off);
        b += __shfl_xor_sync(0xffffffffu, b, off);
        s += __shfl_xor_sync(0xffffffffu, s, off);
    }
    if (t == 0) {
        out[0] = -b / (float)BATCH;                  // bpr
        out[1] = 1e-4f * 0.5f * s / (float)BATCH;    // reg
        out[2] = 0.5f * l / (float)BATCH;            // na
    }
}

extern "C" void kernel_launch(void* const* d_in, const int* in_sizes, int n_in,
                              void* d_out, int out_size)
{
    const float* ut  = (const float*)d_in[0];
    const float* it  = (const float*)d_in[1];
    const int* user  = (const int*)d_in[2];
    const int* pos   = (const int*)d_in[3];
    const int* neg   = (const int*)d_in[4];

    prep_kernel<<<BATCH / 8, 256>>>(ut, it, user, pos, neg);
    dim3 grid(NCB, NCB);
    gemm_kernel<<<grid, 256>>>();
    rowloss_kernel<<<NCB, 128>>>();
    final_kernel<<<1, 32>>>((float*)d_out);
}

// round 4
// speedup vs baseline: 9.7315x; 1.1142x over previous
#include <cuda_runtime.h>
#include <cuda_bf16.h>

// LightCSCF: bpr + reg + cscf losses.
// total = e1@e2^T + e1@e1^T = e1 @ (e1+e2)^T -> single 8192x8192x64 GEMM on
// bf16 tensor cores (mma.sync m16n8k16, fp32 accum), fused epilogue
// g(x) = exp(x/T) + max(1, exp(x/T)*exp(-m/T)) and fused row-sum.
// R4: (a) __launch_bounds__(256,2) to guarantee 2 CTA/SM overlap,
//     (b) 5*log2e scale folded into the A operand -> epilogue is raw ex2,
//     (c) rowloss+final fused via last-block pattern,
//     (d) g_partial transposed to column-block-major (coalesced both ways).

#define BATCH 8192
#define DIM   64
#define NCB   64          // 8192 / 128 column blocks
#define PITCH 72          // smem row pitch in bf16 (144B -> ldmatrix conflict-free)

#define SCALE_A 7.2134752044f      // 5 * log2(e):  exp(5x) = ex2(SCALE_A * x)
#define C_MARG  0.0183156393f      // exp(-margin/T) = exp(-4)

__device__ __nv_bfloat16 g_e1h[BATCH * DIM]; // SCALE_A * normalized user emb (bf16)
__device__ __nv_bfloat16 g_fh [BATCH * DIM]; // e1 + e2 (bf16)
__device__ float g_pos[BATCH];               // cscf pos_score per row (fp32)
__device__ float g_bpr[BATCH];               // log_sigmoid(pos-neg) per row
__device__ float g_sq [BATCH];               // sum-of-squares per row
__device__ float g_partial[NCB * BATCH];     // [cb][row] row-sum partials
__device__ float g_blk[NCB * 3];             // per-block (loss, bpr, sq) sums
__device__ unsigned g_ctr = 0;               // last-block counter (reset per call)

__device__ __forceinline__ unsigned smem_u32(const void* p) {
    return (unsigned)__cvta_generic_to_shared(p);
}
__device__ __forceinline__ float ex2f(float x) {
    float y; asm("ex2.approx.f32 %0, %1;" : "=f"(y) : "f"(x)); return y;
}

// ---------------------------------------------------------------------------
// Kernel 1: gather + per-row stats + bf16 operand tables. One warp per row.
// ---------------------------------------------------------------------------
__global__ void __launch_bounds__(256) prep_kernel(
    const float* __restrict__ ut, const float* __restrict__ it,
    const int* __restrict__ user, const int* __restrict__ pos,
    const int* __restrict__ neg)
{
    int row  = blockIdx.x * 8 + (threadIdx.x >> 5);
    int lane = threadIdx.x & 31;

    const float2* up  = (const float2*)(ut + (long long)user[row] * DIM);
    const float2* pp  = (const float2*)(it + (long long)pos[row]  * DIM);
    const float2* npp = (const float2*)(it + (long long)neg[row]  * DIM);
    float2 u = up[lane], p = pp[lane], n = npp[lane];

    float s_up = u.x * p.x + u.y * p.y;
    float s_un = u.x * n.x + u.y * n.y;
    float s_uu = u.x * u.x + u.y * u.y;
    float s_pp = p.x * p.x + p.y * p.y;
    float s_nn = n.x * n.x + n.y * n.y;

    #pragma unroll
    for (int off = 16; off; off >>= 1) {
        s_up += __shfl_xor_sync(0xffffffffu, s_up, off);
        s_un += __shfl_xor_sync(0xffffffffu, s_un, off);
        s_uu += __shfl_xor_sync(0xffffffffu, s_uu, off);
        s_pp += __shfl_xor_sync(0xffffffffu, s_pp, off);
        s_nn += __shfl_xor_sync(0xffffffffu, s_nn, off);
    }

    float inu = 1.0f / fmaxf(sqrtf(s_uu), 1e-12f);
    float inp = 1.0f / fmaxf(sqrtf(s_pp), 1e-12f);

    float2 e1; e1.x = u.x * inu;  e1.y = u.y * inu;
    float2 e2; e2.x = p.x * inp;  e2.y = p.y * inp;
    float2 f;  f.x  = e1.x + e2.x; f.y = e1.y + e2.y;

    // A operand pre-scaled by 5*log2e so the epilogue is a bare ex2.
    ((__nv_bfloat162*)(g_e1h + row * DIM))[lane] =
        __floats2bfloat162_rn(e1.x * SCALE_A, e1.y * SCALE_A);
    ((__nv_bfloat162*)(g_fh  + row * DIM))[lane] =
        __floats2bfloat162_rn(f.x, f.y);

    if (lane == 0) {
        float sim = s_up * inu * inp;
        float t = __expf(sim * 5.0f);
        g_pos[row] = t + fmaxf(1.0f, t * C_MARG);
        float x = s_up - s_un;
        g_bpr[row] = fminf(x, 0.0f) - log1pf(__expf(-fabsf(x)));
        g_sq[row] = s_uu + s_pp + s_nn;
    }
}

// ---------------------------------------------------------------------------
// Kernel 2: tensor-core GEMM + fused epilogue + row-sum.
// 128x128 tile per CTA, 8 warps (4x2), warp tile 32x64. Forced 2 CTA/SM.
// ---------------------------------------------------------------------------
__global__ void __launch_bounds__(256, 2) gemm_kernel()
{
    __shared__ __align__(16) __nv_bfloat16 a_s[128 * PITCH];
    __shared__ __align__(16) __nv_bfloat16 b_s[128 * PITCH];
    __shared__ float rowsum[2][128];

    int tid = threadIdx.x;
    int rowBase = blockIdx.y * 128;
    int colBase = blockIdx.x * 128;

    const uint4* ga = (const uint4*)g_e1h;
    const uint4* gb = (const uint4*)g_fh;
    #pragma unroll
    for (int l = 0; l < 4; l++) {
        int i = tid + l * 256;       // 0..1023
        int r = i >> 3;              // 0..127
        int c = i & 7;               // 0..7 (16B chunks)
        *(uint4*)&a_s[r * PITCH + c * 8] = ga[(rowBase + r) * 8 + c];
        *(uint4*)&b_s[r * PITCH + c * 8] = gb[(colBase + r) * 8 + c];
    }
    __syncthreads();

    int wid  = tid >> 5;
    int lane = tid & 31;
    int wy = wid >> 1;   // rows wy*32 .. +31
    int wx = wid & 1;    // cols wx*64 .. +63

    float acc[2][8][4];
    #pragma unroll
    for (int mf = 0; mf < 2; mf++)
        #pragma unroll
        for (int nf = 0; nf < 8; nf++)
            #pragma unroll
            for (int q = 0; q < 4; q++) acc[mf][nf][q] = 0.0f;

    unsigned a_base = smem_u32(a_s) +
        (wy * 32 + (lane & 15)) * (PITCH * 2) + (lane >> 4) * 16;
    unsigned b_base = smem_u32(b_s) +
        (wx * 64 + (lane & 15)) * (PITCH * 2) + (lane >> 4) * 16;

    #pragma unroll
    for (int s = 0; s < 4; s++) {            // k16 steps over K=64
        unsigned koff = s * 32;

        unsigned af[2][4];
        #pragma unroll
        for (int mf = 0; mf < 2; mf++) {
            unsigned addr = a_base + mf * 16 * (PITCH * 2) + koff;
            asm volatile("ldmatrix.sync.aligned.m8n8.x4.shared.b16 "
                         "{%0,%1,%2,%3}, [%4];"
                         : "=r"(af[mf][0]), "=r"(af[mf][1]),
                           "=r"(af[mf][2]), "=r"(af[mf][3])
                         : "r"(addr));
        }

        unsigned bf[8][2];
        #pragma unroll
        for (int g = 0; g < 4; g++) {
            unsigned addr = b_base + g * 16 * (PITCH * 2) + koff;
            unsigned r0, r1, r2, r3;
            asm volatile("ldmatrix.sync.aligned.m8n8.x4.shared.b16 "
                         "{%0,%1,%2,%3}, [%4];"
                         : "=r"(r0), "=r"(r1), "=r"(r2), "=r"(r3)
                         : "r"(addr));
            bf[g * 2 + 0][0] = r0; bf[g * 2 + 0][1] = r2;
            bf[g * 2 + 1][0] = r1; bf[g * 2 + 1][1] = r3;
        }

        #pragma unroll
        for (int mf = 0; mf < 2; mf++)
            #pragma unroll
            for (int nf = 0; nf < 8; nf++)
                asm volatile(
                    "mma.sync.aligned.m16n8k16.row.col.f32.bf16.bf16.f32 "
                    "{%0,%1,%2,%3}, {%4,%5,%6,%7}, {%8,%9}, {%0,%1,%2,%3};"
                    : "+f"(acc[mf][nf][0]), "+f"(acc[mf][nf][1]),
                      "+f"(acc[mf][nf][2]), "+f"(acc[mf][nf][3])
                    : "r"(af[mf][0]), "r"(af[mf][1]),
                      "r"(af[mf][2]), "r"(af[mf][3]),
                      "r"(bf[nf][0]), "r"(bf[nf][1]));
    }

    // Epilogue: acc already = 5*log2e * sim -> t = ex2(acc).
    // g = t + max(1, t*C); fused row-sum.
    #pragma unroll
    for (int mf = 0; mf < 2; mf++) {
        float rs0 = 0.0f, rs1 = 0.0f;
        #pragma unroll
        for (int nf = 0; nf < 8; nf++) {
            #pragma unroll
            for (int q = 0; q < 2; q++) {
                float t = ex2f(acc[mf][nf][q]);
                rs0 += t + fmaxf(1.0f, t * C_MARG);
            }
            #pragma unroll
            for (int q = 2; q < 4; q++) {
                float t = ex2f(acc[mf][nf][q]);
                rs1 += t + fmaxf(1.0f, t * C_MARG);
            }
        }
        #pragma unroll
        for (int off = 1; off <= 2; off <<= 1) {
            rs0 += __shfl_xor_sync(0xffffffffu, rs0, off);
            rs1 += __shfl_xor_sync(0xffffffffu, rs1, off);
        }
        if ((lane & 3) == 0) {
            int r = wy * 32 + mf * 16 + (lane >> 2);
            rowsum[wx][r]     = rs0;
            rowsum[wx][r + 8] = rs1;
        }
    }
    __syncthreads();

    if (tid < 128)   // column-block-major: coalesced write AND read
        g_partial[blockIdx.x * BATCH + rowBase + tid] =
            rowsum[0][tid] + rowsum[1][tid];
}

// ---------------------------------------------------------------------------
// Kernel 3: per-row loss + block sums + last-block final reduction.
// ---------------------------------------------------------------------------
__global__ void __launch_bounds__(128) rowloss_final_kernel(float* __restrict__ out)
{
    int tid = threadIdx.x;
    int row = blockIdx.x * 128 + tid;

    float rs = 0.0f;
    #pragma unroll
    for (int cb = 0; cb < NCB; cb++)        // coalesced across threads
        rs += g_partial[cb * BATCH + row];

    float loss = -logf(g_pos[row] / rs + 1e-5f);
    float bpr = g_bpr[row];
    float sq  = g_sq[row];

    __shared__ float sl[128], sb[128], ss[128];
    sl[tid] = loss; sb[tid] = bpr; ss[tid] = sq;
    __syncthreads();
    #pragma unroll
    for (int s = 64; s; s >>= 1) {
        if (tid < s) {
            sl[tid] += sl[tid + s];
            sb[tid] += sb[tid + s];
            ss[tid] += ss[tid + s];
        }
        __syncthreads();
    }

    __shared__ unsigned isLast;
    if (tid == 0) {
        g_blk[blockIdx.x * 3 + 0] = sl[0];
        g_blk[blockIdx.x * 3 + 1] = sb[0];
        g_blk[blockIdx.x * 3 + 2] = ss[0];
        __threadfence();
        isLast = (atomicAdd(&g_ctr, 1u) == (unsigned)(gridDim.x - 1));
    }
    __syncthreads();

    if (isLast) {
        __threadfence();
        if (tid < 32) {
            float l = 0.0f, b = 0.0f, s = 0.0f;
            for (int i = tid; i < NCB; i += 32) {   // fixed order -> deterministic
                l += g_blk[i * 3 + 0];
                b += g_blk[i * 3 + 1];
                s += g_blk[i * 3 + 2];
            }
            #pragma unroll
            for (int off = 16; off; off >>= 1) {
                l += __shfl_xor_sync(0xffffffffu, l, off);
                b += __shfl_xor_sync(0xffffffffu, b, off);
                s += __shfl_xor_sync(0xffffffffu, s, off);
            }
            if (tid == 0) {
                out[0] = -b / (float)BATCH;               // bpr
                out[1] = 1e-4f * 0.5f * s / (float)BATCH; // reg
                out[2] = 0.5f * l / (float)BATCH;         // na
                g_ctr = 0;                                // reset for next replay
            }
        }
    }
}

extern "C" void kernel_launch(void* const* d_in, const int* in_sizes, int n_in,
                              void* d_out, int out_size)
{
    const float* ut  = (const float*)d_in[0];
    const float* it  = (const float*)d_in[1];
    const int* user  = (const int*)d_in[2];
    const int* pos   = (const int*)d_in[3];
    const int* neg   = (const int*)d_in[4];

    prep_kernel<<<BATCH / 8, 256>>>(ut, it, user, pos, neg);
    dim3 grid(NCB, NCB);
    gemm_kernel<<<grid, 256>>>();
    rowloss_final_kernel<<<NCB, 128>>>((float*)d_out);
}

// round 5
// speedup vs baseline: 10.8801x; 1.1180x over previous
#include <cuda_runtime.h>
#include <cuda_bf16.h>

// LightCSCF: bpr + reg + cscf losses.
// total = e1@e2^T + e1@e1^T = e1 @ (e1+e2)^T -> single 8192x8192x64 GEMM on
// bf16 tensor cores, fused epilogue g(x)=t+max(1,t*C), t=ex2(acc), fused row-sum.
// R5: multi-tile CTAs (A reuse x4), cp.async double-buffered B (loads overlap
//     compute), warp tile 16x128 (single row owner -> no smem rowsum), XOR
//     swizzle pitch-64 smem (A + 2xB = 48KB exactly), 2 CTA/SM.

#define BATCH 8192
#define DIM   64
#define NCB   64            // 8192 / 128 column blocks
#define TILES_PER_CTA 4     // column tiles per CTA
#define NSTRIPE (NCB / TILES_PER_CTA)   // 16 grid.x

#define SCALE_A 7.2134752044f      // 5 * log2(e)
#define C_MARG  0.0183156393f      // exp(-margin/T) = exp(-4)

__device__ __nv_bfloat16 g_e1h[BATCH * DIM]; // SCALE_A * normalized user emb (bf16)
__device__ __nv_bfloat16 g_fh [BATCH * DIM]; // e1 + e2 (bf16)
__device__ float g_pos[BATCH];
__device__ float g_bpr[BATCH];
__device__ float g_sq [BATCH];
__device__ float g_partial[NCB * BATCH];     // [cb][row]
__device__ float g_blk[NCB * 3];
__device__ unsigned g_ctr = 0;

__device__ __forceinline__ unsigned smem_u32(const void* p) {
    return (unsigned)__cvta_generic_to_shared(p);
}
__device__ __forceinline__ float ex2f(float x) {
    float y; asm("ex2.approx.f32 %0, %1;" : "=f"(y) : "f"(x)); return y;
}
__device__ __forceinline__ void cp16(unsigned dst, const void* src) {
    asm volatile("cp.async.cg.shared.global [%0], [%1], 16;"
                 :: "r"(dst), "l"(src));
}
__device__ __forceinline__ void cp_commit() {
    asm volatile("cp.async.commit_group;");
}
__device__ __forceinline__ void cp_wait0() {
    asm volatile("cp.async.wait_group 0;");
}

// ---------------------------------------------------------------------------
// Kernel 1: gather + per-row stats + bf16 operand tables. One warp per row.
// ---------------------------------------------------------------------------
__global__ void __launch_bounds__(256) prep_kernel(
    const float* __restrict__ ut, const float* __restrict__ it,
    const int* __restrict__ user, const int* __restrict__ pos,
    const int* __restrict__ neg)
{
    int row  = blockIdx.x * 8 + (threadIdx.x >> 5);
    int lane = threadIdx.x & 31;

    const float2* up  = (const float2*)(ut + (long long)user[row] * DIM);
    const float2* pp  = (const float2*)(it + (long long)pos[row]  * DIM);
    const float2* npp = (const float2*)(it + (long long)neg[row]  * DIM);
    float2 u = up[lane], p = pp[lane], n = npp[lane];

    float s_up = u.x * p.x + u.y * p.y;
    float s_un = u.x * n.x + u.y * n.y;
    float s_uu = u.x * u.x + u.y * u.y;
    float s_pp = p.x * p.x + p.y * p.y;
    float s_nn = n.x * n.x + n.y * n.y;

    #pragma unroll
    for (int off = 16; off; off >>= 1) {
        s_up += __shfl_xor_sync(0xffffffffu, s_up, off);
        s_un += __shfl_xor_sync(0xffffffffu, s_un, off);
        s_uu += __shfl_xor_sync(0xffffffffu, s_uu, off);
        s_pp += __shfl_xor_sync(0xffffffffu, s_pp, off);
        s_nn += __shfl_xor_sync(0xffffffffu, s_nn, off);
    }

    float inu = 1.0f / fmaxf(sqrtf(s_uu), 1e-12f);
    float inp = 1.0f / fmaxf(sqrtf(s_pp), 1e-12f);

    float2 e1; e1.x = u.x * inu;  e1.y = u.y * inu;
    float2 e2; e2.x = p.x * inp;  e2.y = p.y * inp;
    float2 f;  f.x  = e1.x + e2.x; f.y = e1.y + e2.y;

    ((__nv_bfloat162*)(g_e1h + row * DIM))[lane] =
        __floats2bfloat162_rn(e1.x * SCALE_A, e1.y * SCALE_A);
    ((__nv_bfloat162*)(g_fh  + row * DIM))[lane] =
        __floats2bfloat162_rn(f.x, f.y);

    if (lane == 0) {
        float sim = s_up * inu * inp;
        float t = __expf(sim * 5.0f);
        g_pos[row] = t + fmaxf(1.0f, t * C_MARG);
        float x = s_up - s_un;
        g_bpr[row] = fminf(x, 0.0f) - log1pf(__expf(-fabsf(x)));
        g_sq[row] = s_uu + s_pp + s_nn;
    }
}

// ---------------------------------------------------------------------------
// Kernel 2: tensor GEMM + fused epilogue + row-sum.
// grid (NSTRIPE, 64). CTA: fixed 128-row block, 4 col tiles, A loaded once,
// B double-buffered with cp.async. 8 warps, warp tile 16x128.
// smem layout per tile: row r (128B) holds K=64 bf16, 16B chunk c stored at
// chunk (c ^ (r&7)) -> ldmatrix conflict-free without padding.
// ---------------------------------------------------------------------------
__global__ void __launch_bounds__(256, 2) gemm_kernel()
{
    __shared__ __align__(128) __nv_bfloat16 a_s[128 * DIM];
    __shared__ __align__(128) __nv_bfloat16 b_s[2][128 * DIM];

    int tid = threadIdx.x;
    int rowBase = blockIdx.y * 128;
    int cb0 = blockIdx.x * TILES_PER_CTA;

    unsigned a_base = smem_u32(a_s);
    unsigned b_base0 = smem_u32(b_s[0]);
    unsigned b_base1 = smem_u32(b_s[1]);

    // Stage A (once) and B tile 0. 1024 16B-chunks each, 4 per thread.
    {
        const char* ga = (const char*)(g_e1h + rowBase * DIM);
        const char* gb = (const char*)(g_fh + (cb0 * 128) * DIM);
        #pragma unroll
        for (int l = 0; l < 4; l++) {
            int i = tid + l * 256;            // 0..1023
            int r = i >> 3, c = i & 7;
            unsigned soff = (unsigned)(r * 128 + ((c ^ (r & 7)) << 4));
            cp16(a_base + soff, ga + r * 128 + c * 16);
            cp16(b_base0 + soff, gb + r * 128 + c * 16);
        }
        cp_commit();
        cp_wait0();
    }
    __syncthreads();

    int wid  = tid >> 5;            // warp: rows wid*16 .. +15
    int lane = tid & 31;
    int lr   = lane & 15;           // frag row within 16
    int h    = lane >> 4;           // k-half selector
    int x7   = lane & 7;            // swizzle xor

    unsigned a_row = a_base + (wid * 16 + lr) * 128;

    #pragma unroll 1
    for (int t = 0; t < TILES_PER_CTA; t++) {
        unsigned b_cur = (t & 1) ? b_base1 : b_base0;
        unsigned b_nxt = (t & 1) ? b_base0 : b_base1;

        // Prefetch next B tile (overlaps mma + epilogue below).
        if (t + 1 < TILES_PER_CTA) {
            const char* gb = (const char*)(g_fh + ((cb0 + t + 1) * 128) * DIM);
            #pragma unroll
            for (int l = 0; l < 4; l++) {
                int i = tid + l * 256;
                int r = i >> 3, c = i & 7;
                unsigned soff = (unsigned)(r * 128 + ((c ^ (r & 7)) << 4));
                cp16(b_nxt + soff, gb + r * 128 + c * 16);
            }
            cp_commit();
        }

        float acc[16][4];
        #pragma unroll
        for (int nf = 0; nf < 16; nf++)
            #pragma unroll
            for (int q = 0; q < 4; q++) acc[nf][q] = 0.0f;

        #pragma unroll
        for (int s = 0; s < 4; s++) {         // k16 steps over K=64
            unsigned sw = (unsigned)(((2 * s + h) ^ x7) << 4);

            unsigned af[4];
            asm volatile("ldmatrix.sync.aligned.m8n8.x4.shared.b16 "
                         "{%0,%1,%2,%3}, [%4];"
                         : "=r"(af[0]), "=r"(af[1]), "=r"(af[2]), "=r"(af[3])
                         : "r"(a_row + sw));

            #pragma unroll
            for (int g = 0; g < 8; g++) {     // 128 cols = 8 x (16-col frag)
                unsigned addr = b_cur + (g * 16 + lr) * 128 + sw;
                unsigned r0, r1, r2, r3;
                asm volatile("ldmatrix.sync.aligned.m8n8.x4.shared.b16 "
                             "{%0,%1,%2,%3}, [%4];"
                             : "=r"(r0), "=r"(r1), "=r"(r2), "=r"(r3)
                             : "r"(addr));
                asm volatile(
                    "mma.sync.aligned.m16n8k16.row.col.f32.bf16.bf16.f32 "
                    "{%0,%1,%2,%3}, {%4,%5,%6,%7}, {%8,%9}, {%0,%1,%2,%3};"
                    : "+f"(acc[2*g][0]), "+f"(acc[2*g][1]),
                      "+f"(acc[2*g][2]), "+f"(acc[2*g][3])
                    : "r"(af[0]), "r"(af[1]), "r"(af[2]), "r"(af[3]),
                      "r"(r0), "r"(r2));
                asm volatile(
                    "mma.sync.aligned.m16n8k16.row.col.f32.bf16.bf16.f32 "
                    "{%0,%1,%2,%3}, {%4,%5,%6,%7}, {%8,%9}, {%0,%1,%2,%3};"
                    : "+f"(acc[2*g+1][0]), "+f"(acc[2*g+1][1]),
                      "+f"(acc[2*g+1][2]), "+f"(acc[2*g+1][3])
                    : "r"(af[0]), "r"(af[1]), "r"(af[2]), "r"(af[3]),
                      "r"(r1), "r"(r3));
            }
        }

        // Epilogue: t_e = ex2(acc); g = t_e + max(1, t_e*C); row-sum.
        float rs0 = 0.0f, rs1 = 0.0f;
        #pragma unroll
        for (int nf = 0; nf < 16; nf++) {
            float t0 = ex2f(acc[nf][0]);
            float t1 = ex2f(acc[nf][1]);
            float t2 = ex2f(acc[nf][2]);
            float t3 = ex2f(acc[nf][3]);
            rs0 += t0 + fmaxf(1.0f, t0 * C_MARG);
            rs0 += t1 + fmaxf(1.0f, t1 * C_MARG);
            rs1 += t2 + fmaxf(1.0f, t2 * C_MARG);
            rs1 += t3 + fmaxf(1.0f, t3 * C_MARG);
        }
        #pragma unroll
        for (int off = 1; off <= 2; off <<= 1) {
            rs0 += __shfl_xor_sync(0xffffffffu, rs0, off);
            rs1 += __shfl_xor_sync(0xffffffffu, rs1, off);
        }
        if ((lane & 3) == 0) {
            int r0 = rowBase + wid * 16 + (lane >> 2);
            int cb = cb0 + t;
            g_partial[cb * BATCH + r0]     = rs0;
            g_partial[cb * BATCH + r0 + 8] = rs1;
        }

        if (t + 1 < TILES_PER_CTA) {
            cp_wait0();
            __syncthreads();
        }
    }
}

// ---------------------------------------------------------------------------
// Kernel 3: per-row loss + block sums + last-block final reduction.
// ---------------------------------------------------------------------------
__global__ void __launch_bounds__(128) rowloss_final_kernel(float* __restrict__ out)
{
    int tid = threadIdx.x;
    int row = blockIdx.x * 128 + tid;

    float rs = 0.0f;
    #pragma unroll
    for (int cb = 0; cb < NCB; cb++)
        rs += g_partial[cb * BATCH + row];

    float loss = -logf(g_pos[row] / rs + 1e-5f);
    float bpr = g_bpr[row];
    float sq  = g_sq[row];

    __shared__ float sl[128], sb[128], ss[128];
    sl[tid] = loss; sb[tid] = bpr; ss[tid] = sq;
    __syncthreads();
    #pragma unroll
    for (int s = 64; s; s >>= 1) {
        if (tid < s) {
            sl[tid] += sl[tid + s];
            sb[tid] += sb[tid + s];
            ss[tid] += ss[tid + s];
        }
        __syncthreads();
    }

    __shared__ unsigned isLast;
    if (tid == 0) {
        g_blk[blockIdx.x * 3 + 0] = sl[0];
        g_blk[blockIdx.x * 3 + 1] = sb[0];
        g_blk[blockIdx.x * 3 + 2] = ss[0];
        __threadfence();
        isLast = (atomicAdd(&g_ctr, 1u) == (unsigned)(gridDim.x - 1));
    }
    __syncthreads();

    if (isLast) {
        __threadfence();
        if (tid < 32) {
            float l = 0.0f, b = 0.0f, s = 0.0f;
            for (int i = tid; i < NCB; i += 32) {
                l += g_blk[i * 3 + 0];
                b += g_blk[i * 3 + 1];
                s += g_blk[i * 3 + 2];
            }
            #pragma unroll
            for (int off = 16; off; off >>= 1) {
                l += __shfl_xor_sync(0xffffffffu, l, off);
                b += __shfl_xor_sync(0xffffffffu, b, off);
                s += __shfl_xor_sync(0xffffffffu, s, off);
            }
            if (tid == 0) {
                out[0] = -b / (float)BATCH;
                out[1] = 1e-4f * 0.5f * s / (float)BATCH;
                out[2] = 0.5f * l / (float)BATCH;
                g_ctr = 0;
            }
        }
    }
}

extern "C" void kernel_launch(void* const* d_in, const int* in_sizes, int n_in,
                              void* d_out, int out_size)
{
    const float* ut  = (const float*)d_in[0];
    const float* it  = (const float*)d_in[1];
    const int* user  = (const int*)d_in[2];
    const int* pos   = (const int*)d_in[3];
    const int* neg   = (const int*)d_in[4];

    prep_kernel<<<BATCH / 8, 256>>>(ut, it, user, pos, neg);
    dim3 grid(NSTRIPE, NCB);
    gemm_kernel<<<grid, 256>>>();
    rowloss_final_kernel<<<NCB, 128>>>((float*)d_out);
}